// round 15
// baseline (speedup 1.0000x reference)
#include <cuda_runtime.h>
#include <math.h>

#define BQ 2048
#define NP 1000
#define TOPK 32

typedef unsigned long long u64;
typedef unsigned int u32;

// ---------------- device scratch (allocation-free) ----------------
__device__ float g_mean[BQ * 64];
__device__ float g_bias1[BQ * 128];
__device__ float g_obsbias[BQ * 64];
__device__ float g_logw[BQ * NP];
__device__ __align__(16) float g_W1img[16384];  // W1^T [128n][64k] hi|lo, swizzled
__device__ __align__(16) float g_W2img[16384];  // W2^T [64n][128k] hi|lo, sigma+swizzled
__device__ __align__(16) float g_W3img[8192];   // W3^T [64n][64k]  hi|lo, sigma+swizzled

__device__ __forceinline__ float gelu_exact(float x) {
    return 0.5f * x * (1.0f + erff(x * 0.7071067811865476f));
}
__device__ __forceinline__ u64 splat2(float x) {
    u64 r; asm("mov.b64 %0,{%1,%1};" : "=l"(r) : "f"(x)); return r;
}
__device__ __forceinline__ u64 pack2(float lo, float hi) {
    u64 r; asm("mov.b64 %0,{%1,%2};" : "=l"(r) : "f"(lo), "f"(hi)); return r;
}
__device__ __forceinline__ void unpack2(u64 v, float& lo, float& hi) {
    asm("mov.b64 {%0,%1},%2;" : "=f"(lo), "=f"(hi) : "l"(v));
}
__device__ __forceinline__ void fma2(u64& d, u64 a, u64 b) {
    asm("fma.rn.f32x2 %0,%1,%2,%0;" : "+l"(d) : "l"(a), "l"(b));
}
__device__ __forceinline__ void tf32split(float v, float& hi, float& lo) {
    hi = __uint_as_float(__float_as_uint(v) & 0xFFFFE000u);
    lo = v - hi;
}
// m16n8k8 tf32 mma: D += A*B, acc fp32
__device__ __forceinline__ void mma8(float* d, u32 a0, u32 a1, u32 a2, u32 a3,
                                     u32 b0, u32 b1) {
    asm volatile(
        "mma.sync.aligned.m16n8k8.row.col.f32.tf32.tf32.f32 "
        "{%0,%1,%2,%3},{%4,%5,%6,%7},{%8,%9},{%0,%1,%2,%3};"
        : "+f"(d[0]), "+f"(d[1]), "+f"(d[2]), "+f"(d[3])
        : "r"(a0), "r"(a1), "r"(a2), "r"(a3), "r"(b0), "r"(b1));
}

// smem float offsets for k_big
#define SW1H   0
#define SW1L   8192
#define SW2H   16384
#define SW2L   24576
#define SW3H   32768
#define SW3L   36864
#define SEXCH  40960     /* 4 regions x 2176 floats */
#define SBIAS1 49664
#define SBT2   49792
#define SOBIAS 49856
#define SW4    49920
#define SMEM_BIG_FL 49984
#define SMEM_BIG_BYTES (SMEM_BIG_FL * 4)

// ---------------------------------------------------------------------------
// k_prep: build tf32-split, swizzled (and sigma-permuted for W2/W3) images
// sigma within each 8-block: actual k=2c -> slot c ; k=2c+1 -> slot c+4
// ---------------------------------------------------------------------------
__global__ void k_prep(const float* __restrict__ W_t1, const float* __restrict__ W_t2,
                       const float* __restrict__ W_w1) {
    int tid = threadIdx.x;
    for (int i = tid; i < 8192; i += 256) {          // W1: n 0..127, k 0..63 (no sigma)
        int n = i >> 6, k = i & 63;
        float v = W_t1[k * 128 + n], hi, lo; tf32split(v, hi, lo);
        int pos = n * 64 + (k ^ ((n & 7) << 2));
        g_W1img[pos] = hi; g_W1img[8192 + pos] = lo;
    }
    for (int i = tid; i < 8192; i += 256) {          // W2: n 0..63, k 0..127 (sigma)
        int n = i >> 7, k = i & 127;
        float v = W_t2[k * 64 + n], hi, lo; tf32split(v, hi, lo);
        int j = k & 7;
        int slot = (j & 1) ? ((j >> 1) + 4) : (j >> 1);
        int kk = (k & ~7) | slot;
        int pos = n * 128 + (kk ^ ((n & 7) << 2));
        g_W2img[pos] = hi; g_W2img[8192 + pos] = lo;
    }
    for (int i = tid; i < 4096; i += 256) {          // W3: n 0..63, k 0..63 (sigma)
        int n = i >> 6, k = i & 63;
        float v = W_w1[k * 64 + n], hi, lo; tf32split(v, hi, lo);
        int j = k & 7;
        int slot = (j & 1) ? ((j >> 1) + 4) : (j >> 1);
        int kk = (k & ~7) | slot;
        int pos = n * 64 + (kk ^ ((n & 7) << 2));
        g_W3img[pos] = hi; g_W3img[4096 + pos] = lo;
    }
}

// ---------------------------------------------------------------------------
// Kernel 1: mean of particles_init * 0.1
// ---------------------------------------------------------------------------
__global__ void k_mean(const float* __restrict__ X) {
    int b = blockIdx.x;
    int tid = threadIdx.x;
    int q = tid >> 4, d4 = tid & 15;
    const float4* base = (const float4*)(X + (size_t)b * NP * 64);
    float4 acc = make_float4(0.f, 0.f, 0.f, 0.f);
    for (int n = q; n < NP; n += 16) {
        float4 v = base[n * 16 + d4];
        acc.x += v.x; acc.y += v.y; acc.z += v.z; acc.w += v.w;
    }
    __shared__ float s[16][64];
    *(float4*)&s[q][d4 * 4] = acc;
    __syncthreads();
    if (tid < 64) {
        float sum = 0.f;
        #pragma unroll
        for (int i = 0; i < 16; i++) sum += s[i][tid];
        g_mean[b * 64 + tid] = sum * (0.1f / 1000.0f);
    }
}

// ---------------------------------------------------------------------------
// Kernel 2: obs encoder, regime softmax, fused per-batch biases
// ---------------------------------------------------------------------------
__global__ void k_small(const float* __restrict__ obs,
                        const float* __restrict__ W_obs1, const float* __restrict__ b_obs1,
                        const float* __restrict__ W_obs2, const float* __restrict__ b_obs2,
                        const float* __restrict__ W_t1,   const float* __restrict__ b_t1,
                        const float* __restrict__ W_w1,   const float* __restrict__ b_w1,
                        const float* __restrict__ W_r,    const float* __restrict__ b_r,
                        float* __restrict__ out, int write_probs) {
    int b = blockIdx.x, tid = threadIdx.x;
    __shared__ float obs_s[256], h[128], enc[64], probs[4], m[64];
    obs_s[tid]       = obs[b * 256 + tid];
    obs_s[tid + 128] = obs[b * 256 + 128 + tid];
    if (tid < 64) m[tid] = g_mean[b * 64 + tid];
    __syncthreads();
    {
        float acc = b_obs1[tid];
        for (int j = 0; j < 256; j++) acc = fmaf(obs_s[j], W_obs1[j * 128 + tid], acc);
        h[tid] = gelu_exact(acc);
    }
    __syncthreads();
    if (tid < 64) {
        float a2 = b_obs2[tid];
        for (int j = 0; j < 128; j++) a2 = fmaf(h[j], W_obs2[j * 64 + tid], a2);
        enc[tid] = a2;
    }
    if (tid >= 64 && tid < 68) {
        int k = tid - 64;
        float lg = b_r[k];
        for (int d = 0; d < 64; d++) lg = fmaf(m[d], W_r[d * 4 + k], lg);
        probs[k] = lg;
    }
    __syncthreads();
    if (tid == 0) {
        float mx = fmaxf(fmaxf(probs[0], probs[1]), fmaxf(probs[2], probs[3]));
        float e0 = expf(probs[0] - mx), e1 = expf(probs[1] - mx);
        float e2 = expf(probs[2] - mx), e3 = expf(probs[3] - mx);
        float z = e0 + e1 + e2 + e3;
        probs[0] = e0 / z; probs[1] = e1 / z; probs[2] = e2 / z; probs[3] = e3 / z;
    }
    __syncthreads();
    {
        float bb = b_t1[tid];
        #pragma unroll
        for (int k = 0; k < 4; k++) bb = fmaf(probs[k], W_t1[(64 + k) * 128 + tid], bb);
        g_bias1[b * 128 + tid] = bb;
    }
    if (tid < 64) {
        float ob = b_w1[tid];
        for (int j = 0; j < 64; j++) ob = fmaf(enc[j], W_w1[(64 + j) * 64 + tid], ob);
        g_obsbias[b * 64 + tid] = ob;
    }
    if (write_probs && tid < 4) out[BQ * 64 + b * 4 + tid] = probs[tid];
}

// ---------------------------------------------------------------------------
// Kernel 3: fused MLP chain via mma.sync 3xTF32. One CTA per batch, 8 tiles.
// Warp (rw = warp>>1, cw = warp&1): rows 32*rw..+31, stage1 cols 64*cw..+63.
// Stage chaining stays in registers via sigma-permuted weight images.
// ---------------------------------------------------------------------------
__global__ void __launch_bounds__(256, 1)
k_big(const float* __restrict__ X, const float* __restrict__ b_t2,
      const float* __restrict__ W_w2, const float* __restrict__ b_w2) {
    extern __shared__ float sm[];
    int tid = threadIdx.x, b = blockIdx.x;
    int warp = tid >> 5, lane = tid & 31;
    int rw = warp >> 1, cw = warp & 1;
    int q = lane >> 2, cq = lane & 3, xm = q << 2;

    {   // weight images -> smem
        float4* d = (float4*)sm;
        const float4* s1 = (const float4*)g_W1img;
        for (int i = tid; i < 4096; i += 256) d[i] = s1[i];
        const float4* s2 = (const float4*)g_W2img;
        for (int i = tid; i < 4096; i += 256) d[4096 + i] = s2[i];
        const float4* s3 = (const float4*)g_W3img;
        for (int i = tid; i < 2048; i += 256) d[8192 + i] = s3[i];
    }
    if (tid < 128) sm[SBIAS1 + tid] = g_bias1[b * 128 + tid];
    else if (tid < 192) sm[SBT2 + tid - 128] = b_t2[tid - 128];
    else sm[SOBIAS + tid - 192] = g_obsbias[b * 64 + tid - 192];
    if (tid < 64) sm[SW4 + tid] = W_w2[tid];
    float bw = b_w2[0];
    __syncthreads();

    const float* W1h = sm + SW1H; const float* W1l = sm + SW1L;
    const float* W2h = sm + SW2H; const float* W2l = sm + SW2L;
    const float* W3h = sm + SW3H; const float* W3l = sm + SW3L;
    float* exch = sm + SEXCH + rw * 2176;

    const float* Xb = X + (size_t)b * NP * 64;

    for (int t = 0; t < 8; t++) {
        int n0 = t * 128;

        // ================= stage 1: D1 = 0.1X @ W1 (cols 64cw..64cw+63) ======
        float acc1[2][8][4];
        #pragma unroll
        for (int rt = 0; rt < 2; rt++)
            #pragma unroll
            for (int c = 0; c < 8; c++)
                #pragma unroll
                for (int r = 0; r < 4; r++) acc1[rt][c][r] = 0.f;

        for (int kt = 0; kt < 8; kt++) {
            u32 ah[2][4], al[2][4];
            #pragma unroll
            for (int rt = 0; rt < 2; rt++) {
                int r0 = 32 * rw + 16 * rt + q, r1 = r0 + 8;
                int kb = kt * 8 + cq;
                float x0 = 0.f, x1 = 0.f, x2 = 0.f, x3 = 0.f;
                if (n0 + r0 < NP) { x0 = Xb[(size_t)(n0 + r0) * 64 + kb];
                                    x2 = Xb[(size_t)(n0 + r0) * 64 + kb + 4]; }
                if (n0 + r1 < NP) { x1 = Xb[(size_t)(n0 + r1) * 64 + kb];
                                    x3 = Xb[(size_t)(n0 + r1) * 64 + kb + 4]; }
                float h0, l0, h1, l1, h2, l2, h3, l3;
                tf32split(0.1f * x0, h0, l0); tf32split(0.1f * x1, h1, l1);
                tf32split(0.1f * x2, h2, l2); tf32split(0.1f * x3, h3, l3);
                ah[rt][0] = __float_as_uint(h0); ah[rt][1] = __float_as_uint(h1);
                ah[rt][2] = __float_as_uint(h2); ah[rt][3] = __float_as_uint(h3);
                al[rt][0] = __float_as_uint(l0); al[rt][1] = __float_as_uint(l1);
                al[rt][2] = __float_as_uint(l2); al[rt][3] = __float_as_uint(l3);
            }
            #pragma unroll
            for (int ct = 0; ct < 8; ct++) {
                int nb = (64 * cw + 8 * ct + q) * 64;
                int o0 = (8 * kt + cq) ^ xm, o1 = (8 * kt + cq + 4) ^ xm;
                u32 bh0 = __float_as_uint(W1h[nb + o0]);
                u32 bh1 = __float_as_uint(W1h[nb + o1]);
                u32 bl0 = __float_as_uint(W1l[nb + o0]);
                u32 bl1 = __float_as_uint(W1l[nb + o1]);
                #pragma unroll
                for (int rt = 0; rt < 2; rt++) {
                    mma8(acc1[rt][ct], ah[rt][0], ah[rt][1], ah[rt][2], ah[rt][3], bh0, bh1);
                    mma8(acc1[rt][ct], al[rt][0], al[rt][1], al[rt][2], al[rt][3], bh0, bh1);
                    mma8(acc1[rt][ct], ah[rt][0], ah[rt][1], ah[rt][2], ah[rt][3], bl0, bl1);
                }
            }
        }

        // ================= stage 2: partial D2 over k = own 64 cols ==========
        // A-frags from acc1 d-regs: (a0,a1,a2,a3) = (g(d0), g(d2), g(d1), g(d3))
        float acc2[2][8][4];
        #pragma unroll
        for (int rt = 0; rt < 2; rt++)
            #pragma unroll
            for (int c = 0; c < 8; c++)
                #pragma unroll
                for (int r = 0; r < 4; r++) acc2[rt][c][r] = 0.f;

        #pragma unroll
        for (int kt2 = 0; kt2 < 8; kt2++) {
            int c0 = 64 * cw + 8 * kt2 + 2 * cq;
            float bb0 = sm[SBIAS1 + c0], bb1 = sm[SBIAS1 + c0 + 1];
            u32 ah[2][4], al[2][4];
            #pragma unroll
            for (int rt = 0; rt < 2; rt++) {
                float g0 = gelu_exact(acc1[rt][kt2][0] + bb0);
                float g1 = gelu_exact(acc1[rt][kt2][1] + bb1);
                float g2 = gelu_exact(acc1[rt][kt2][2] + bb0);
                float g3 = gelu_exact(acc1[rt][kt2][3] + bb1);
                float h0, l0, h1, l1, h2, l2, h3, l3;
                tf32split(g0, h0, l0); tf32split(g2, h1, l1);   // a1 <- d2
                tf32split(g1, h2, l2);                          // a2 <- d1
                tf32split(g3, h3, l3);
                ah[rt][0] = __float_as_uint(h0); ah[rt][1] = __float_as_uint(h1);
                ah[rt][2] = __float_as_uint(h2); ah[rt][3] = __float_as_uint(h3);
                al[rt][0] = __float_as_uint(l0); al[rt][1] = __float_as_uint(l1);
                al[rt][2] = __float_as_uint(l2); al[rt][3] = __float_as_uint(l3);
            }
            int kg0 = (64 * cw + 8 * kt2 + cq) ^ xm;
            int kg1 = (64 * cw + 8 * kt2 + cq + 4) ^ xm;
            #pragma unroll
            for (int nt = 0; nt < 8; nt++) {
                int nb = (8 * nt + q) * 128;
                u32 bh0 = __float_as_uint(W2h[nb + kg0]);
                u32 bh1 = __float_as_uint(W2h[nb + kg1]);
                u32 bl0 = __float_as_uint(W2l[nb + kg0]);
                u32 bl1 = __float_as_uint(W2l[nb + kg1]);
                #pragma unroll
                for (int rt = 0; rt < 2; rt++) {
                    mma8(acc2[rt][nt], ah[rt][0], ah[rt][1], ah[rt][2], ah[rt][3], bh0, bh1);
                    mma8(acc2[rt][nt], al[rt][0], al[rt][1], al[rt][2], al[rt][3], bh0, bh1);
                    mma8(acc2[rt][nt], ah[rt][0], ah[rt][1], ah[rt][2], ah[rt][3], bl0, bl1);
                }
            }
        }

        // ---- exchange: P2 = partial(cw0) + partial(cw1) + b_t2, both warps ----
        if (cw == 0) {
            #pragma unroll
            for (int rt = 0; rt < 2; rt++)
                #pragma unroll
                for (int nt = 0; nt < 8; nt++)
                    *(float4*)&exch[lane * 68 + rt * 32 + nt * 4] =
                        make_float4(acc2[rt][nt][0], acc2[rt][nt][1],
                                    acc2[rt][nt][2], acc2[rt][nt][3]);
        }
        __syncthreads();
        if (cw == 1) {
            #pragma unroll
            for (int rt = 0; rt < 2; rt++)
                #pragma unroll
                for (int nt = 0; nt < 8; nt++) {
                    float4 v = *(float4*)&exch[lane * 68 + rt * 32 + nt * 4];
                    float t0 = sm[SBT2 + 8 * nt + 2 * cq], t1 = sm[SBT2 + 8 * nt + 2 * cq + 1];
                    acc2[rt][nt][0] += v.x + t0;
                    acc2[rt][nt][1] += v.y + t1;
                    acc2[rt][nt][2] += v.z + t0;
                    acc2[rt][nt][3] += v.w + t1;
                    *(float4*)&exch[lane * 68 + rt * 32 + nt * 4] =
                        make_float4(acc2[rt][nt][0], acc2[rt][nt][1],
                                    acc2[rt][nt][2], acc2[rt][nt][3]);
                }
        }
        __syncthreads();
        if (cw == 0) {
            #pragma unroll
            for (int rt = 0; rt < 2; rt++)
                #pragma unroll
                for (int nt = 0; nt < 8; nt++) {
                    float4 v = *(float4*)&exch[lane * 68 + rt * 32 + nt * 4];
                    acc2[rt][nt][0] = v.x; acc2[rt][nt][1] = v.y;
                    acc2[rt][nt][2] = v.z; acc2[rt][nt][3] = v.w;
                }
        }

        // ================= stage 3: partial D3 over k-half = 4cw..4cw+3 ======
        float acc3[2][8][4];
        #pragma unroll
        for (int rt = 0; rt < 2; rt++)
            #pragma unroll
            for (int c = 0; c < 8; c++)
                #pragma unroll
                for (int r = 0; r < 4; r++) acc3[rt][c][r] = 0.f;

        #pragma unroll
        for (int j = 0; j < 4; j++) {
            u32 ah[2][4], al[2][4];
            #pragma unroll
            for (int rt = 0; rt < 2; rt++) {
                float d0 = cw ? acc2[rt][4 + j][0] : acc2[rt][j][0];
                float d1 = cw ? acc2[rt][4 + j][1] : acc2[rt][j][1];
                float d2 = cw ? acc2[rt][4 + j][2] : acc2[rt][j][2];
                float d3 = cw ? acc2[rt][4 + j][3] : acc2[rt][j][3];
                float h0, l0, h1, l1, h2, l2, h3, l3;
                tf32split(d0, h0, l0); tf32split(d2, h1, l1);
                tf32split(d1, h2, l2); tf32split(d3, h3, l3);
                ah[rt][0] = __float_as_uint(h0); ah[rt][1] = __float_as_uint(h1);
                ah[rt][2] = __float_as_uint(h2); ah[rt][3] = __float_as_uint(h3);
                al[rt][0] = __float_as_uint(l0); al[rt][1] = __float_as_uint(l1);
                al[rt][2] = __float_as_uint(l2); al[rt][3] = __float_as_uint(l3);
            }
            int ktg = 4 * cw + j;
            int kg0 = (8 * ktg + cq) ^ xm, kg1 = (8 * ktg + cq + 4) ^ xm;
            #pragma unroll
            for (int nt = 0; nt < 8; nt++) {
                int nb = (8 * nt + q) * 64;
                u32 bh0 = __float_as_uint(W3h[nb + kg0]);
                u32 bh1 = __float_as_uint(W3h[nb + kg1]);
                u32 bl0 = __float_as_uint(W3l[nb + kg0]);
                u32 bl1 = __float_as_uint(W3l[nb + kg1]);
                #pragma unroll
                for (int rt = 0; rt < 2; rt++) {
                    mma8(acc3[rt][nt], ah[rt][0], ah[rt][1], ah[rt][2], ah[rt][3], bh0, bh1);
                    mma8(acc3[rt][nt], al[rt][0], al[rt][1], al[rt][2], al[rt][3], bh0, bh1);
                    mma8(acc3[rt][nt], ah[rt][0], ah[rt][1], ah[rt][2], ah[rt][3], bl0, bl1);
                }
            }
        }

        // ---- stage 4: combine halves, gelu, dot w4, row-reduce, store ----
        if (cw == 0) {
            #pragma unroll
            for (int rt = 0; rt < 2; rt++)
                #pragma unroll
                for (int nt = 0; nt < 8; nt++)
                    *(float4*)&exch[lane * 68 + rt * 32 + nt * 4] =
                        make_float4(acc3[rt][nt][0], acc3[rt][nt][1],
                                    acc3[rt][nt][2], acc3[rt][nt][3]);
        }
        __syncthreads();
        if (cw == 1) {
            #pragma unroll
            for (int rt = 0; rt < 2; rt++) {
                float pa = 0.f, pb = 0.f;
                #pragma unroll
                for (int nt = 0; nt < 8; nt++) {
                    float4 v = *(float4*)&exch[lane * 68 + rt * 32 + nt * 4];
                    int nc = 8 * nt + 2 * cq;
                    float ob0 = sm[SOBIAS + nc], ob1 = sm[SOBIAS + nc + 1];
                    float w40 = sm[SW4 + nc],   w41 = sm[SW4 + nc + 1];
                    pa = fmaf(gelu_exact(acc3[rt][nt][0] + v.x + ob0), w40, pa);
                    pa = fmaf(gelu_exact(acc3[rt][nt][1] + v.y + ob1), w41, pa);
                    pb = fmaf(gelu_exact(acc3[rt][nt][2] + v.z + ob0), w40, pb);
                    pb = fmaf(gelu_exact(acc3[rt][nt][3] + v.w + ob1), w41, pb);
                }
                pa += __shfl_xor_sync(0xffffffffu, pa, 1);
                pa += __shfl_xor_sync(0xffffffffu, pa, 2);
                pb += __shfl_xor_sync(0xffffffffu, pb, 1);
                pb += __shfl_xor_sync(0xffffffffu, pb, 2);
                if (cq == 0) {
                    int r0 = n0 + 32 * rw + 16 * rt + q;
                    if (r0 < NP)     g_logw[b * NP + r0]     = pa + bw;
                    if (r0 + 8 < NP) g_logw[b * NP + r0 + 8] = pb + bw;
                }
            }
        }
        __syncthreads();
    }
}

// ---------------------------------------------------------------------------
// Kernel 4: softmax + top-32 + commuted weighted recompute (unchanged)
// ---------------------------------------------------------------------------
__global__ void __launch_bounds__(256, 1)
k_final(const float* __restrict__ X,
        const float* __restrict__ W_t1, const float* __restrict__ W_t2,
        const float* __restrict__ b_t2, float* __restrict__ out) {
    extern __shared__ float smf[];
    float* W1s   = smf;
    float* W2s   = W1s + 8192;
    float* lw    = W2s + 8192;
    float* bias1 = lw + 1024;
    float* bt2s  = bias1 + 128;
    float* xr    = bt2s + 64;
    float* h1s   = xr + 2048;
    float* hbar  = h1s + 4224;
    float* red2  = hbar + 128;
    float* red   = red2 + 256;
    int*   redi  = (int*)(red + 8);
    float* selw  = (float*)(redi + 8);
    int*   seli  = (int*)(selw + 32);
    float* bcast = (float*)(seli + 32);

    int b = blockIdx.x, tid = threadIdx.x;
    int lane = tid & 31, warp = tid >> 5;

    for (int i = tid; i < 8192; i += 256) { W1s[i] = W_t1[i]; W2s[i] = W_t2[i]; }
    if (tid < 128) bias1[tid] = g_bias1[b * 128 + tid];
    if (tid < 64)  bt2s[tid]  = b_t2[tid];
    for (int i = tid; i < 1024; i += 256)
        lw[i] = (i < NP) ? g_logw[b * NP + i] : -INFINITY;
    __syncthreads();

    float lmax = -INFINITY;
    #pragma unroll
    for (int m = 0; m < 4; m++) lmax = fmaxf(lmax, lw[tid + 256 * m]);
    #pragma unroll
    for (int off = 16; off >= 1; off >>= 1)
        lmax = fmaxf(lmax, __shfl_xor_sync(0xffffffffu, lmax, off));
    if (lane == 0) red[warp] = lmax;
    __syncthreads();
    if (tid == 0) {
        float mx = red[0];
        for (int w = 1; w < 8; w++) mx = fmaxf(mx, red[w]);
        bcast[0] = mx;
    }
    __syncthreads();
    float mx = bcast[0];

    float ls = 0.f;
    #pragma unroll
    for (int m = 0; m < 4; m++) ls += expf(lw[tid + 256 * m] - mx);
    #pragma unroll
    for (int off = 16; off >= 1; off >>= 1)
        ls += __shfl_xor_sync(0xffffffffu, ls, off);
    if (lane == 0) red[warp] = ls;
    __syncthreads();
    if (tid == 0) {
        float z = 0.f;
        for (int w = 0; w < 8; w++) z += red[w];
        bcast[1] = z;
        bcast[2] = 0.f;
    }
    __syncthreads();
    float Z = bcast[1];

    for (int it = 0; it < TOPK; it++) {
        float v = -INFINITY; int vi = 0x7fffffff;
        #pragma unroll
        for (int m = 0; m < 4; m++) {
            int i = tid + 256 * m;
            float x = lw[i];
            if (x > v || (x == v && i < vi)) { v = x; vi = i; }
        }
        #pragma unroll
        for (int off = 16; off >= 1; off >>= 1) {
            float ov = __shfl_xor_sync(0xffffffffu, v, off);
            int   oi = __shfl_xor_sync(0xffffffffu, vi, off);
            if (ov > v || (ov == v && oi < vi)) { v = ov; vi = oi; }
        }
        if (lane == 0) { red[warp] = v; redi[warp] = vi; }
        __syncthreads();
        if (tid == 0) {
            float bv = red[0]; int bi = redi[0];
            for (int w = 1; w < 8; w++)
                if (red[w] > bv || (red[w] == bv && redi[w] < bi)) { bv = red[w]; bi = redi[w]; }
            seli[it] = bi;
            float wv = expf(bv - mx) / Z;
            selw[it] = wv;
            bcast[2] += wv;
            lw[bi] = -INFINITY;
        }
        __syncthreads();
    }

    for (int i = tid; i < TOPK * 16; i += 256) {
        int s = i >> 4, d4 = i & 15;
        float4 v = ((const float4*)(X + ((size_t)b * NP + seli[s]) * 64))[d4];
        *(float4*)&xr[s * 64 + d4 * 4] =
            make_float4(0.1f * v.x, 0.1f * v.y, 0.1f * v.z, 0.1f * v.w);
    }
    __syncthreads();

    {
        int s0 = (tid >> 4) * 2;
        int c0 = (tid & 15) * 8;
        u64 accA[8];
        #pragma unroll
        for (int j = 0; j < 8; j++) accA[j] = 0ull;
        #pragma unroll 4
        for (int k = 0; k < 64; k++) {
            u64 xp = pack2(xr[s0 * 64 + k], xr[s0 * 64 + 64 + k]);
            float4 b0 = *(const float4*)&W1s[k * 128 + c0];
            float4 b1 = *(const float4*)&W1s[k * 128 + c0 + 4];
            u64 bs[8] = {splat2(b0.x), splat2(b0.y), splat2(b0.z), splat2(b0.w),
                         splat2(b1.x), splat2(b1.y), splat2(b1.z), splat2(b1.w)};
            #pragma unroll
            for (int j = 0; j < 8; j++) fma2(accA[j], xp, bs[j]);
        }
        #pragma unroll
        for (int j = 0; j < 8; j++) {
            int col = c0 + j;
            float lo, hi; unpack2(accA[j], lo, hi);
            float bb = bias1[col];
            h1s[s0 * 132 + col]       = gelu_exact(lo + bb);
            h1s[(s0 + 1) * 132 + col] = gelu_exact(hi + bb);
        }
    }
    __syncthreads();

    if (tid < 128) {
        float a = 0.f;
        #pragma unroll 8
        for (int s = 0; s < TOPK; s++) a = fmaf(selw[s], h1s[s * 132 + tid], a);
        hbar[tid] = a;
    }
    __syncthreads();

    {
        int d = tid & 63, jg = tid >> 6;
        float a = 0.f;
        #pragma unroll 8
        for (int jj = 0; jj < 32; jj++) {
            int j = jg * 32 + jj;
            a = fmaf(hbar[j], W2s[j * 64 + d], a);
        }
        red2[jg * 64 + d] = a;
    }
    __syncthreads();
    if (tid < 64) {
        float sumw = bcast[2];
        out[b * 64 + tid] = red2[tid] + red2[64 + tid] + red2[128 + tid]
                          + red2[192 + tid] + sumw * bt2s[tid];
    }
}

// ---------------------------------------------------------------------------
extern "C" void kernel_launch(void* const* d_in, const int* in_sizes, int n_in,
                              void* d_out, int out_size) {
    const float* obs    = (const float*)d_in[0];
    const float* X      = (const float*)d_in[1];
    const float* W_obs1 = (const float*)d_in[2];
    const float* b_obs1 = (const float*)d_in[3];
    const float* W_obs2 = (const float*)d_in[4];
    const float* b_obs2 = (const float*)d_in[5];
    const float* W_t1   = (const float*)d_in[6];
    const float* b_t1   = (const float*)d_in[7];
    const float* W_t2   = (const float*)d_in[8];
    const float* b_t2   = (const float*)d_in[9];
    const float* W_w1   = (const float*)d_in[10];
    const float* b_w1   = (const float*)d_in[11];
    const float* W_w2   = (const float*)d_in[12];
    const float* b_w2   = (const float*)d_in[13];
    const float* W_r    = (const float*)d_in[14];
    const float* b_r    = (const float*)d_in[15];
    float* out = (float*)d_out;

    size_t sm_fin = (size_t)(8192 + 8192 + 1024 + 128 + 64 + 2048 + 4224
                             + 128 + 256 + 8 + 8 + 32 + 32 + 4 + 32) * sizeof(float);
    cudaFuncSetAttribute(k_big,   cudaFuncAttributeMaxDynamicSharedMemorySize, SMEM_BIG_BYTES);
    cudaFuncSetAttribute(k_final, cudaFuncAttributeMaxDynamicSharedMemorySize, (int)sm_fin);

    int write_probs = (out_size >= BQ * 64 + BQ * 4) ? 1 : 0;

    k_prep<<<1, 256>>>(W_t1, W_t2, W_w1);
    k_mean<<<BQ, 256>>>(X);
    k_small<<<BQ, 128>>>(obs, W_obs1, b_obs1, W_obs2, b_obs2,
                         W_t1, b_t1, W_w1, b_w1, W_r, b_r, out, write_probs);
    k_big<<<BQ, 256, SMEM_BIG_BYTES>>>(X, b_t2, W_w2, b_w2);
    k_final<<<BQ, 256, sm_fin>>>(X, W_t1, W_t2, b_t2, out);
}

// round 16
// speedup vs baseline: 1.0009x; 1.0009x over previous
#include <cuda_runtime.h>
#include <math.h>

#define BQ 2048
#define NP 1000
#define TOPK 32

typedef unsigned long long u64;
typedef unsigned int u32;

// ---------------- device scratch (allocation-free) ----------------
__device__ float g_mean[BQ * 64];
__device__ float g_bias1[BQ * 128];
__device__ float g_obsbias[BQ * 64];
__device__ float g_logw[BQ * NP];
__device__ __align__(16) float g_W1img[16384];  // W1^T [128n][64k] hi|lo, swizzled
__device__ __align__(16) float g_W2img[16384];  // W2^T [64n][128k] hi|lo, sigma+swizzled
__device__ __align__(16) float g_W3img[8192];   // W3^T [64n][64k]  hi|lo, sigma+swizzled

__device__ __forceinline__ float gelu_exact(float x) {
    return 0.5f * x * (1.0f + erff(x * 0.7071067811865476f));
}
__device__ __forceinline__ u64 splat2(float x) {
    u64 r; asm("mov.b64 %0,{%1,%1};" : "=l"(r) : "f"(x)); return r;
}
__device__ __forceinline__ u64 pack2(float lo, float hi) {
    u64 r; asm("mov.b64 %0,{%1,%2};" : "=l"(r) : "f"(lo), "f"(hi)); return r;
}
__device__ __forceinline__ void unpack2(u64 v, float& lo, float& hi) {
    asm("mov.b64 {%0,%1},%2;" : "=f"(lo), "=f"(hi) : "l"(v));
}
__device__ __forceinline__ void fma2(u64& d, u64 a, u64 b) {
    asm("fma.rn.f32x2 %0,%1,%2,%0;" : "+l"(d) : "l"(a), "l"(b));
}
__device__ __forceinline__ void tf32split(float v, float& hi, float& lo) {
    hi = __uint_as_float(__float_as_uint(v) & 0xFFFFE000u);
    lo = v - hi;
}
// m16n8k8 tf32 mma: D += A*B, acc fp32
__device__ __forceinline__ void mma8(float* d, u32 a0, u32 a1, u32 a2, u32 a3,
                                     u32 b0, u32 b1) {
    asm volatile(
        "mma.sync.aligned.m16n8k8.row.col.f32.tf32.tf32.f32 "
        "{%0,%1,%2,%3},{%4,%5,%6,%7},{%8,%9},{%0,%1,%2,%3};"
        : "+f"(d[0]), "+f"(d[1]), "+f"(d[2]), "+f"(d[3])
        : "r"(a0), "r"(a1), "r"(a2), "r"(a3), "r"(b0), "r"(b1));
}

// smem float offsets for k_big
#define SW1H   0
#define SW1L   8192
#define SW2H   16384
#define SW2L   24576
#define SW3H   32768
#define SW3L   36864
#define SEXCH  40960     /* 4 regions x 2176 floats */
#define SBIAS1 49664
#define SBT2   49792
#define SOBIAS 49856
#define SW4    49920
#define SMEM_BIG_FL 49984
#define SMEM_BIG_BYTES (SMEM_BIG_FL * 4)

// ---------------------------------------------------------------------------
// k_prep: build tf32-split, swizzled (and sigma-permuted for W2/W3) images
// sigma within each 8-block: actual k=2c -> slot c ; k=2c+1 -> slot c+4
// ---------------------------------------------------------------------------
__global__ void k_prep(const float* __restrict__ W_t1, const float* __restrict__ W_t2,
                       const float* __restrict__ W_w1) {
    int tid = threadIdx.x;
    for (int i = tid; i < 8192; i += 256) {          // W1: n 0..127, k 0..63 (no sigma)
        int n = i >> 6, k = i & 63;
        float v = W_t1[k * 128 + n], hi, lo; tf32split(v, hi, lo);
        int pos = n * 64 + (k ^ ((n & 7) << 2));
        g_W1img[pos] = hi; g_W1img[8192 + pos] = lo;
    }
    for (int i = tid; i < 8192; i += 256) {          // W2: n 0..63, k 0..127 (sigma)
        int n = i >> 7, k = i & 127;
        float v = W_t2[k * 64 + n], hi, lo; tf32split(v, hi, lo);
        int j = k & 7;
        int slot = (j & 1) ? ((j >> 1) + 4) : (j >> 1);
        int kk = (k & ~7) | slot;
        int pos = n * 128 + (kk ^ ((n & 7) << 2));
        g_W2img[pos] = hi; g_W2img[8192 + pos] = lo;
    }
    for (int i = tid; i < 4096; i += 256) {          // W3: n 0..63, k 0..63 (sigma)
        int n = i >> 6, k = i & 63;
        float v = W_w1[k * 64 + n], hi, lo; tf32split(v, hi, lo);
        int j = k & 7;
        int slot = (j & 1) ? ((j >> 1) + 4) : (j >> 1);
        int kk = (k & ~7) | slot;
        int pos = n * 64 + (kk ^ ((n & 7) << 2));
        g_W3img[pos] = hi; g_W3img[4096 + pos] = lo;
    }
}

// ---------------------------------------------------------------------------
// Kernel 1: mean of particles_init * 0.1
// ---------------------------------------------------------------------------
__global__ void k_mean(const float* __restrict__ X) {
    int b = blockIdx.x;
    int tid = threadIdx.x;
    int q = tid >> 4, d4 = tid & 15;
    const float4* base = (const float4*)(X + (size_t)b * NP * 64);
    float4 acc = make_float4(0.f, 0.f, 0.f, 0.f);
    for (int n = q; n < NP; n += 16) {
        float4 v = base[n * 16 + d4];
        acc.x += v.x; acc.y += v.y; acc.z += v.z; acc.w += v.w;
    }
    __shared__ float s[16][64];
    *(float4*)&s[q][d4 * 4] = acc;
    __syncthreads();
    if (tid < 64) {
        float sum = 0.f;
        #pragma unroll
        for (int i = 0; i < 16; i++) sum += s[i][tid];
        g_mean[b * 64 + tid] = sum * (0.1f / 1000.0f);
    }
}

// ---------------------------------------------------------------------------
// Kernel 2: obs encoder, regime softmax, fused per-batch biases
// ---------------------------------------------------------------------------
__global__ void k_small(const float* __restrict__ obs,
                        const float* __restrict__ W_obs1, const float* __restrict__ b_obs1,
                        const float* __restrict__ W_obs2, const float* __restrict__ b_obs2,
                        const float* __restrict__ W_t1,   const float* __restrict__ b_t1,
                        const float* __restrict__ W_w1,   const float* __restrict__ b_w1,
                        const float* __restrict__ W_r,    const float* __restrict__ b_r,
                        float* __restrict__ out, int write_probs) {
    int b = blockIdx.x, tid = threadIdx.x;
    __shared__ float obs_s[256], h[128], enc[64], probs[4], m[64];
    obs_s[tid]       = obs[b * 256 + tid];
    obs_s[tid + 128] = obs[b * 256 + 128 + tid];
    if (tid < 64) m[tid] = g_mean[b * 64 + tid];
    __syncthreads();
    {
        float acc = b_obs1[tid];
        for (int j = 0; j < 256; j++) acc = fmaf(obs_s[j], W_obs1[j * 128 + tid], acc);
        h[tid] = gelu_exact(acc);
    }
    __syncthreads();
    if (tid < 64) {
        float a2 = b_obs2[tid];
        for (int j = 0; j < 128; j++) a2 = fmaf(h[j], W_obs2[j * 64 + tid], a2);
        enc[tid] = a2;
    }
    if (tid >= 64 && tid < 68) {
        int k = tid - 64;
        float lg = b_r[k];
        for (int d = 0; d < 64; d++) lg = fmaf(m[d], W_r[d * 4 + k], lg);
        probs[k] = lg;
    }
    __syncthreads();
    if (tid == 0) {
        float mx = fmaxf(fmaxf(probs[0], probs[1]), fmaxf(probs[2], probs[3]));
        float e0 = expf(probs[0] - mx), e1 = expf(probs[1] - mx);
        float e2 = expf(probs[2] - mx), e3 = expf(probs[3] - mx);
        float z = e0 + e1 + e2 + e3;
        probs[0] = e0 / z; probs[1] = e1 / z; probs[2] = e2 / z; probs[3] = e3 / z;
    }
    __syncthreads();
    {
        float bb = b_t1[tid];
        #pragma unroll
        for (int k = 0; k < 4; k++) bb = fmaf(probs[k], W_t1[(64 + k) * 128 + tid], bb);
        g_bias1[b * 128 + tid] = bb;
    }
    if (tid < 64) {
        float ob = b_w1[tid];
        for (int j = 0; j < 64; j++) ob = fmaf(enc[j], W_w1[(64 + j) * 64 + tid], ob);
        g_obsbias[b * 64 + tid] = ob;
    }
    if (write_probs && tid < 4) out[BQ * 64 + b * 4 + tid] = probs[tid];
}

// ---------------------------------------------------------------------------
// Kernel 3: fused MLP chain via mma.sync 3xTF32. One CTA per batch, 8 tiles.
// Warp (rw = warp>>1, cw = warp&1): rows 32*rw..+31, stage1 cols 64*cw..+63.
// Stage chaining stays in registers via sigma-permuted weight images.
// ---------------------------------------------------------------------------
__global__ void __launch_bounds__(256, 1)
k_big(const float* __restrict__ X, const float* __restrict__ b_t2,
      const float* __restrict__ W_w2, const float* __restrict__ b_w2) {
    extern __shared__ float sm[];
    int tid = threadIdx.x, b = blockIdx.x;
    int warp = tid >> 5, lane = tid & 31;
    int rw = warp >> 1, cw = warp & 1;
    int q = lane >> 2, cq = lane & 3, xm = q << 2;

    {   // weight images -> smem
        float4* d = (float4*)sm;
        const float4* s1 = (const float4*)g_W1img;
        for (int i = tid; i < 4096; i += 256) d[i] = s1[i];
        const float4* s2 = (const float4*)g_W2img;
        for (int i = tid; i < 4096; i += 256) d[4096 + i] = s2[i];
        const float4* s3 = (const float4*)g_W3img;
        for (int i = tid; i < 2048; i += 256) d[8192 + i] = s3[i];
    }
    if (tid < 128) sm[SBIAS1 + tid] = g_bias1[b * 128 + tid];
    else if (tid < 192) sm[SBT2 + tid - 128] = b_t2[tid - 128];
    else sm[SOBIAS + tid - 192] = g_obsbias[b * 64 + tid - 192];
    if (tid < 64) sm[SW4 + tid] = W_w2[tid];
    float bw = b_w2[0];
    __syncthreads();

    const float* W1h = sm + SW1H; const float* W1l = sm + SW1L;
    const float* W2h = sm + SW2H; const float* W2l = sm + SW2L;
    const float* W3h = sm + SW3H; const float* W3l = sm + SW3L;
    float* exch = sm + SEXCH + rw * 2176;

    const float* Xb = X + (size_t)b * NP * 64;

    for (int t = 0; t < 8; t++) {
        int n0 = t * 128;

        // ================= stage 1: D1 = 0.1X @ W1 (cols 64cw..64cw+63) ======
        float acc1[2][8][4];
        #pragma unroll
        for (int rt = 0; rt < 2; rt++)
            #pragma unroll
            for (int c = 0; c < 8; c++)
                #pragma unroll
                for (int r = 0; r < 4; r++) acc1[rt][c][r] = 0.f;

        for (int kt = 0; kt < 8; kt++) {
            u32 ah[2][4], al[2][4];
            #pragma unroll
            for (int rt = 0; rt < 2; rt++) {
                int r0 = 32 * rw + 16 * rt + q, r1 = r0 + 8;
                int kb = kt * 8 + cq;
                float x0 = 0.f, x1 = 0.f, x2 = 0.f, x3 = 0.f;
                if (n0 + r0 < NP) { x0 = Xb[(size_t)(n0 + r0) * 64 + kb];
                                    x2 = Xb[(size_t)(n0 + r0) * 64 + kb + 4]; }
                if (n0 + r1 < NP) { x1 = Xb[(size_t)(n0 + r1) * 64 + kb];
                                    x3 = Xb[(size_t)(n0 + r1) * 64 + kb + 4]; }
                float h0, l0, h1, l1, h2, l2, h3, l3;
                tf32split(0.1f * x0, h0, l0); tf32split(0.1f * x1, h1, l1);
                tf32split(0.1f * x2, h2, l2); tf32split(0.1f * x3, h3, l3);
                ah[rt][0] = __float_as_uint(h0); ah[rt][1] = __float_as_uint(h1);
                ah[rt][2] = __float_as_uint(h2); ah[rt][3] = __float_as_uint(h3);
                al[rt][0] = __float_as_uint(l0); al[rt][1] = __float_as_uint(l1);
                al[rt][2] = __float_as_uint(l2); al[rt][3] = __float_as_uint(l3);
            }
            #pragma unroll
            for (int ct = 0; ct < 8; ct++) {
                int nb = (64 * cw + 8 * ct + q) * 64;
                int o0 = (8 * kt + cq) ^ xm, o1 = (8 * kt + cq + 4) ^ xm;
                u32 bh0 = __float_as_uint(W1h[nb + o0]);
                u32 bh1 = __float_as_uint(W1h[nb + o1]);
                u32 bl0 = __float_as_uint(W1l[nb + o0]);
                u32 bl1 = __float_as_uint(W1l[nb + o1]);
                #pragma unroll
                for (int rt = 0; rt < 2; rt++) {
                    mma8(acc1[rt][ct], ah[rt][0], ah[rt][1], ah[rt][2], ah[rt][3], bh0, bh1);
                    mma8(acc1[rt][ct], al[rt][0], al[rt][1], al[rt][2], al[rt][3], bh0, bh1);
                    mma8(acc1[rt][ct], ah[rt][0], ah[rt][1], ah[rt][2], ah[rt][3], bl0, bl1);
                }
            }
        }

        // ================= stage 2: partial D2 over k = own 64 cols ==========
        // A-frags from acc1 d-regs: (a0,a1,a2,a3) = (g(d0), g(d2), g(d1), g(d3))
        float acc2[2][8][4];
        #pragma unroll
        for (int rt = 0; rt < 2; rt++)
            #pragma unroll
            for (int c = 0; c < 8; c++)
                #pragma unroll
                for (int r = 0; r < 4; r++) acc2[rt][c][r] = 0.f;

        #pragma unroll
        for (int kt2 = 0; kt2 < 8; kt2++) {
            int c0 = 64 * cw + 8 * kt2 + 2 * cq;
            float bb0 = sm[SBIAS1 + c0], bb1 = sm[SBIAS1 + c0 + 1];
            u32 ah[2][4], al[2][4];
            #pragma unroll
            for (int rt = 0; rt < 2; rt++) {
                float g0 = gelu_exact(acc1[rt][kt2][0] + bb0);
                float g1 = gelu_exact(acc1[rt][kt2][1] + bb1);
                float g2 = gelu_exact(acc1[rt][kt2][2] + bb0);
                float g3 = gelu_exact(acc1[rt][kt2][3] + bb1);
                float h0, l0, h1, l1, h2, l2, h3, l3;
                tf32split(g0, h0, l0); tf32split(g2, h1, l1);   // a1 <- d2
                tf32split(g1, h2, l2);                          // a2 <- d1
                tf32split(g3, h3, l3);
                ah[rt][0] = __float_as_uint(h0); ah[rt][1] = __float_as_uint(h1);
                ah[rt][2] = __float_as_uint(h2); ah[rt][3] = __float_as_uint(h3);
                al[rt][0] = __float_as_uint(l0); al[rt][1] = __float_as_uint(l1);
                al[rt][2] = __float_as_uint(l2); al[rt][3] = __float_as_uint(l3);
            }
            int kg0 = (64 * cw + 8 * kt2 + cq) ^ xm;
            int kg1 = (64 * cw + 8 * kt2 + cq + 4) ^ xm;
            #pragma unroll
            for (int nt = 0; nt < 8; nt++) {
                int nb = (8 * nt + q) * 128;
                u32 bh0 = __float_as_uint(W2h[nb + kg0]);
                u32 bh1 = __float_as_uint(W2h[nb + kg1]);
                u32 bl0 = __float_as_uint(W2l[nb + kg0]);
                u32 bl1 = __float_as_uint(W2l[nb + kg1]);
                #pragma unroll
                for (int rt = 0; rt < 2; rt++) {
                    mma8(acc2[rt][nt], ah[rt][0], ah[rt][1], ah[rt][2], ah[rt][3], bh0, bh1);
                    mma8(acc2[rt][nt], al[rt][0], al[rt][1], al[rt][2], al[rt][3], bh0, bh1);
                    mma8(acc2[rt][nt], ah[rt][0], ah[rt][1], ah[rt][2], ah[rt][3], bl0, bl1);
                }
            }
        }

        // ---- exchange: P2 = partial(cw0) + partial(cw1) + b_t2, both warps ----
        if (cw == 0) {
            #pragma unroll
            for (int rt = 0; rt < 2; rt++)
                #pragma unroll
                for (int nt = 0; nt < 8; nt++)
                    *(float4*)&exch[lane * 68 + rt * 32 + nt * 4] =
                        make_float4(acc2[rt][nt][0], acc2[rt][nt][1],
                                    acc2[rt][nt][2], acc2[rt][nt][3]);
        }
        __syncthreads();
        if (cw == 1) {
            #pragma unroll
            for (int rt = 0; rt < 2; rt++)
                #pragma unroll
                for (int nt = 0; nt < 8; nt++) {
                    float4 v = *(float4*)&exch[lane * 68 + rt * 32 + nt * 4];
                    float t0 = sm[SBT2 + 8 * nt + 2 * cq], t1 = sm[SBT2 + 8 * nt + 2 * cq + 1];
                    acc2[rt][nt][0] += v.x + t0;
                    acc2[rt][nt][1] += v.y + t1;
                    acc2[rt][nt][2] += v.z + t0;
                    acc2[rt][nt][3] += v.w + t1;
                    *(float4*)&exch[lane * 68 + rt * 32 + nt * 4] =
                        make_float4(acc2[rt][nt][0], acc2[rt][nt][1],
                                    acc2[rt][nt][2], acc2[rt][nt][3]);
                }
        }
        __syncthreads();
        if (cw == 0) {
            #pragma unroll
            for (int rt = 0; rt < 2; rt++)
                #pragma unroll
                for (int nt = 0; nt < 8; nt++) {
                    float4 v = *(float4*)&exch[lane * 68 + rt * 32 + nt * 4];
                    acc2[rt][nt][0] = v.x; acc2[rt][nt][1] = v.y;
                    acc2[rt][nt][2] = v.z; acc2[rt][nt][3] = v.w;
                }
        }

        // ================= stage 3: partial D3 over k-half = 4cw..4cw+3 ======
        float acc3[2][8][4];
        #pragma unroll
        for (int rt = 0; rt < 2; rt++)
            #pragma unroll
            for (int c = 0; c < 8; c++)
                #pragma unroll
                for (int r = 0; r < 4; r++) acc3[rt][c][r] = 0.f;

        #pragma unroll
        for (int j = 0; j < 4; j++) {
            u32 ah[2][4], al[2][4];
            #pragma unroll
            for (int rt = 0; rt < 2; rt++) {
                float d0 = cw ? acc2[rt][4 + j][0] : acc2[rt][j][0];
                float d1 = cw ? acc2[rt][4 + j][1] : acc2[rt][j][1];
                float d2 = cw ? acc2[rt][4 + j][2] : acc2[rt][j][2];
                float d3 = cw ? acc2[rt][4 + j][3] : acc2[rt][j][3];
                float h0, l0, h1, l1, h2, l2, h3, l3;
                tf32split(d0, h0, l0); tf32split(d2, h1, l1);
                tf32split(d1, h2, l2); tf32split(d3, h3, l3);
                ah[rt][0] = __float_as_uint(h0); ah[rt][1] = __float_as_uint(h1);
                ah[rt][2] = __float_as_uint(h2); ah[rt][3] = __float_as_uint(h3);
                al[rt][0] = __float_as_uint(l0); al[rt][1] = __float_as_uint(l1);
                al[rt][2] = __float_as_uint(l2); al[rt][3] = __float_as_uint(l3);
            }
            int ktg = 4 * cw + j;
            int kg0 = (8 * ktg + cq) ^ xm, kg1 = (8 * ktg + cq + 4) ^ xm;
            #pragma unroll
            for (int nt = 0; nt < 8; nt++) {
                int nb = (8 * nt + q) * 64;
                u32 bh0 = __float_as_uint(W3h[nb + kg0]);
                u32 bh1 = __float_as_uint(W3h[nb + kg1]);
                u32 bl0 = __float_as_uint(W3l[nb + kg0]);
                u32 bl1 = __float_as_uint(W3l[nb + kg1]);
                #pragma unroll
                for (int rt = 0; rt < 2; rt++) {
                    mma8(acc3[rt][nt], ah[rt][0], ah[rt][1], ah[rt][2], ah[rt][3], bh0, bh1);
                    mma8(acc3[rt][nt], al[rt][0], al[rt][1], al[rt][2], al[rt][3], bh0, bh1);
                    mma8(acc3[rt][nt], ah[rt][0], ah[rt][1], ah[rt][2], ah[rt][3], bl0, bl1);
                }
            }
        }

        // ---- stage 4: combine halves, gelu, dot w4, row-reduce, store ----
        if (cw == 0) {
            #pragma unroll
            for (int rt = 0; rt < 2; rt++)
                #pragma unroll
                for (int nt = 0; nt < 8; nt++)
                    *(float4*)&exch[lane * 68 + rt * 32 + nt * 4] =
                        make_float4(acc3[rt][nt][0], acc3[rt][nt][1],
                                    acc3[rt][nt][2], acc3[rt][nt][3]);
        }
        __syncthreads();
        if (cw == 1) {
            #pragma unroll
            for (int rt = 0; rt < 2; rt++) {
                float pa = 0.f, pb = 0.f;
                #pragma unroll
                for (int nt = 0; nt < 8; nt++) {
                    float4 v = *(float4*)&exch[lane * 68 + rt * 32 + nt * 4];
                    int nc = 8 * nt + 2 * cq;
                    float ob0 = sm[SOBIAS + nc], ob1 = sm[SOBIAS + nc + 1];
                    float w40 = sm[SW4 + nc],   w41 = sm[SW4 + nc + 1];
                    pa = fmaf(gelu_exact(acc3[rt][nt][0] + v.x + ob0), w40, pa);
                    pa = fmaf(gelu_exact(acc3[rt][nt][1] + v.y + ob1), w41, pa);
                    pb = fmaf(gelu_exact(acc3[rt][nt][2] + v.z + ob0), w40, pb);
                    pb = fmaf(gelu_exact(acc3[rt][nt][3] + v.w + ob1), w41, pb);
                }
                pa += __shfl_xor_sync(0xffffffffu, pa, 1);
                pa += __shfl_xor_sync(0xffffffffu, pa, 2);
                pb += __shfl_xor_sync(0xffffffffu, pb, 1);
                pb += __shfl_xor_sync(0xffffffffu, pb, 2);
                if (cq == 0) {
                    int r0 = n0 + 32 * rw + 16 * rt + q;
                    if (r0 < NP)     g_logw[b * NP + r0]     = pa + bw;
                    if (r0 + 8 < NP) g_logw[b * NP + r0 + 8] = pb + bw;
                }
            }
        }
        __syncthreads();
    }
}

// ---------------------------------------------------------------------------
// Kernel 4: softmax + top-32 + commuted weighted recompute (unchanged)
// ---------------------------------------------------------------------------
__global__ void __launch_bounds__(256, 1)
k_final(const float* __restrict__ X,
        const float* __restrict__ W_t1, const float* __restrict__ W_t2,
        const float* __restrict__ b_t2, float* __restrict__ out) {
    extern __shared__ float smf[];
    float* W1s   = smf;
    float* W2s   = W1s + 8192;
    float* lw    = W2s + 8192;
    float* bias1 = lw + 1024;
    float* bt2s  = bias1 + 128;
    float* xr    = bt2s + 64;
    float* h1s   = xr + 2048;
    float* hbar  = h1s + 4224;
    float* red2  = hbar + 128;
    float* red   = red2 + 256;
    int*   redi  = (int*)(red + 8);
    float* selw  = (float*)(redi + 8);
    int*   seli  = (int*)(selw + 32);
    float* bcast = (float*)(seli + 32);

    int b = blockIdx.x, tid = threadIdx.x;
    int lane = tid & 31, warp = tid >> 5;

    for (int i = tid; i < 8192; i += 256) { W1s[i] = W_t1[i]; W2s[i] = W_t2[i]; }
    if (tid < 128) bias1[tid] = g_bias1[b * 128 + tid];
    if (tid < 64)  bt2s[tid]  = b_t2[tid];
    for (int i = tid; i < 1024; i += 256)
        lw[i] = (i < NP) ? g_logw[b * NP + i] : -INFINITY;
    __syncthreads();

    float lmax = -INFINITY;
    #pragma unroll
    for (int m = 0; m < 4; m++) lmax = fmaxf(lmax, lw[tid + 256 * m]);
    #pragma unroll
    for (int off = 16; off >= 1; off >>= 1)
        lmax = fmaxf(lmax, __shfl_xor_sync(0xffffffffu, lmax, off));
    if (lane == 0) red[warp] = lmax;
    __syncthreads();
    if (tid == 0) {
        float mx = red[0];
        for (int w = 1; w < 8; w++) mx = fmaxf(mx, red[w]);
        bcast[0] = mx;
    }
    __syncthreads();
    float mx = bcast[0];

    float ls = 0.f;
    #pragma unroll
    for (int m = 0; m < 4; m++) ls += expf(lw[tid + 256 * m] - mx);
    #pragma unroll
    for (int off = 16; off >= 1; off >>= 1)
        ls += __shfl_xor_sync(0xffffffffu, ls, off);
    if (lane == 0) red[warp] = ls;
    __syncthreads();
    if (tid == 0) {
        float z = 0.f;
        for (int w = 0; w < 8; w++) z += red[w];
        bcast[1] = z;
        bcast[2] = 0.f;
    }
    __syncthreads();
    float Z = bcast[1];

    for (int it = 0; it < TOPK; it++) {
        float v = -INFINITY; int vi = 0x7fffffff;
        #pragma unroll
        for (int m = 0; m < 4; m++) {
            int i = tid + 256 * m;
            float x = lw[i];
            if (x > v || (x == v && i < vi)) { v = x; vi = i; }
        }
        #pragma unroll
        for (int off = 16; off >= 1; off >>= 1) {
            float ov = __shfl_xor_sync(0xffffffffu, v, off);
            int   oi = __shfl_xor_sync(0xffffffffu, vi, off);
            if (ov > v || (ov == v && oi < vi)) { v = ov; vi = oi; }
        }
        if (lane == 0) { red[warp] = v; redi[warp] = vi; }
        __syncthreads();
        if (tid == 0) {
            float bv = red[0]; int bi = redi[0];
            for (int w = 1; w < 8; w++)
                if (red[w] > bv || (red[w] == bv && redi[w] < bi)) { bv = red[w]; bi = redi[w]; }
            seli[it] = bi;
            float wv = expf(bv - mx) / Z;
            selw[it] = wv;
            bcast[2] += wv;
            lw[bi] = -INFINITY;
        }
        __syncthreads();
    }

    for (int i = tid; i < TOPK * 16; i += 256) {
        int s = i >> 4, d4 = i & 15;
        float4 v = ((const float4*)(X + ((size_t)b * NP + seli[s]) * 64))[d4];
        *(float4*)&xr[s * 64 + d4 * 4] =
            make_float4(0.1f * v.x, 0.1f * v.y, 0.1f * v.z, 0.1f * v.w);
    }
    __syncthreads();

    {
        int s0 = (tid >> 4) * 2;
        int c0 = (tid & 15) * 8;
        u64 accA[8];
        #pragma unroll
        for (int j = 0; j < 8; j++) accA[j] = 0ull;
        #pragma unroll 4
        for (int k = 0; k < 64; k++) {
            u64 xp = pack2(xr[s0 * 64 + k], xr[s0 * 64 + 64 + k]);
            float4 b0 = *(const float4*)&W1s[k * 128 + c0];
            float4 b1 = *(const float4*)&W1s[k * 128 + c0 + 4];
            u64 bs[8] = {splat2(b0.x), splat2(b0.y), splat2(b0.z), splat2(b0.w),
                         splat2(b1.x), splat2(b1.y), splat2(b1.z), splat2(b1.w)};
            #pragma unroll
            for (int j = 0; j < 8; j++) fma2(accA[j], xp, bs[j]);
        }
        #pragma unroll
        for (int j = 0; j < 8; j++) {
            int col = c0 + j;
            float lo, hi; unpack2(accA[j], lo, hi);
            float bb = bias1[col];
            h1s[s0 * 132 + col]       = gelu_exact(lo + bb);
            h1s[(s0 + 1) * 132 + col] = gelu_exact(hi + bb);
        }
    }
    __syncthreads();

    if (tid < 128) {
        float a = 0.f;
        #pragma unroll 8
        for (int s = 0; s < TOPK; s++) a = fmaf(selw[s], h1s[s * 132 + tid], a);
        hbar[tid] = a;
    }
    __syncthreads();

    {
        int d = tid & 63, jg = tid >> 6;
        float a = 0.f;
        #pragma unroll 8
        for (int jj = 0; jj < 32; jj++) {
            int j = jg * 32 + jj;
            a = fmaf(hbar[j], W2s[j * 64 + d], a);
        }
        red2[jg * 64 + d] = a;
    }
    __syncthreads();
    if (tid < 64) {
        float sumw = bcast[2];
        out[b * 64 + tid] = red2[tid] + red2[64 + tid] + red2[128 + tid]
                          + red2[192 + tid] + sumw * bt2s[tid];
    }
}

// ---------------------------------------------------------------------------
extern "C" void kernel_launch(void* const* d_in, const int* in_sizes, int n_in,
                              void* d_out, int out_size) {
    const float* obs    = (const float*)d_in[0];
    const float* X      = (const float*)d_in[1];
    const float* W_obs1 = (const float*)d_in[2];
    const float* b_obs1 = (const float*)d_in[3];
    const float* W_obs2 = (const float*)d_in[4];
    const float* b_obs2 = (const float*)d_in[5];
    const float* W_t1   = (const float*)d_in[6];
    const float* b_t1   = (const float*)d_in[7];
    const float* W_t2   = (const float*)d_in[8];
    const float* b_t2   = (const float*)d_in[9];
    const float* W_w1   = (const float*)d_in[10];
    const float* b_w1   = (const float*)d_in[11];
    const float* W_w2   = (const float*)d_in[12];
    const float* b_w2   = (const float*)d_in[13];
    const float* W_r    = (const float*)d_in[14];
    const float* b_r    = (const float*)d_in[15];
    float* out = (float*)d_out;

    size_t sm_fin = (size_t)(8192 + 8192 + 1024 + 128 + 64 + 2048 + 4224
                             + 128 + 256 + 8 + 8 + 32 + 32 + 4 + 32) * sizeof(float);
    cudaFuncSetAttribute(k_big,   cudaFuncAttributeMaxDynamicSharedMemorySize, SMEM_BIG_BYTES);
    cudaFuncSetAttribute(k_final, cudaFuncAttributeMaxDynamicSharedMemorySize, (int)sm_fin);

    int write_probs = (out_size >= BQ * 64 + BQ * 4) ? 1 : 0;

    k_prep<<<1, 256>>>(W_t1, W_t2, W_w1);
    k_mean<<<BQ, 256>>>(X);
    k_small<<<BQ, 128>>>(obs, W_obs1, b_obs1, W_obs2, b_obs2,
                         W_t1, b_t1, W_w1, b_w1, W_r, b_r, out, write_probs);
    k_big<<<BQ, 256, SMEM_BIG_BYTES>>>(X, b_t2, W_w2, b_w2);
    k_final<<<BQ, 256, sm_fin>>>(X, W_t1, W_t2, b_t2, out);
}

// round 17
// speedup vs baseline: 1.0025x; 1.0016x over previous
#include <cuda_runtime.h>
#include <math.h>

#define BQ 2048
#define NP 1000
#define TOPK 32

typedef unsigned long long u64;
typedef unsigned int u32;

// ---------------- device scratch (allocation-free) ----------------
__device__ float g_mean[BQ * 64];
__device__ float g_bias1[BQ * 128];
__device__ float g_obsbias[BQ * 64];
__device__ float g_logw[BQ * NP];
__device__ __align__(16) float g_W1img[16384];  // W1^T [128n][64k] hi|lo, swizzled
__device__ __align__(16) float g_W2img[16384];  // W2^T [64n][128k] hi|lo, sigma+swizzled
__device__ __align__(16) float g_W3img[8192];   // W3^T [64n][64k]  hi|lo, sigma+swizzled

__device__ __forceinline__ float gelu_exact(float x) {
    return 0.5f * x * (1.0f + erff(x * 0.7071067811865476f));
}
__device__ __forceinline__ u64 splat2(float x) {
    u64 r; asm("mov.b64 %0,{%1,%1};" : "=l"(r) : "f"(x)); return r;
}
__device__ __forceinline__ u64 pack2(float lo, float hi) {
    u64 r; asm("mov.b64 %0,{%1,%2};" : "=l"(r) : "f"(lo), "f"(hi)); return r;
}
__device__ __forceinline__ void unpack2(u64 v, float& lo, float& hi) {
    asm("mov.b64 {%0,%1},%2;" : "=f"(lo), "=f"(hi) : "l"(v));
}
__device__ __forceinline__ void fma2(u64& d, u64 a, u64 b) {
    asm("fma.rn.f32x2 %0,%1,%2,%0;" : "+l"(d) : "l"(a), "l"(b));
}
__device__ __forceinline__ void tf32split(float v, float& hi, float& lo) {
    hi = __uint_as_float(__float_as_uint(v) & 0xFFFFE000u);
    lo = v - hi;
}
// m16n8k8 tf32 mma: D += A*B, acc fp32
__device__ __forceinline__ void mma8(float* d, u32 a0, u32 a1, u32 a2, u32 a3,
                                     u32 b0, u32 b1) {
    asm volatile(
        "mma.sync.aligned.m16n8k8.row.col.f32.tf32.tf32.f32 "
        "{%0,%1,%2,%3},{%4,%5,%6,%7},{%8,%9},{%0,%1,%2,%3};"
        : "+f"(d[0]), "+f"(d[1]), "+f"(d[2]), "+f"(d[3])
        : "r"(a0), "r"(a1), "r"(a2), "r"(a3), "r"(b0), "r"(b1));
}

// smem float offsets for k_big
#define SW1H   0
#define SW1L   8192
#define SW2H   16384
#define SW2L   24576
#define SW3H   32768
#define SW3L   36864
#define SEXCH  40960     /* 4 regions x 2176 floats */
#define SBIAS1 49664
#define SBT2   49792
#define SOBIAS 49856
#define SW4    49920
#define SMEM_BIG_FL 49984
#define SMEM_BIG_BYTES (SMEM_BIG_FL * 4)

// ---------------------------------------------------------------------------
// k_prep: build tf32-split, swizzled (and sigma-permuted for W2/W3) images
// sigma within each 8-block: actual k=2c -> slot c ; k=2c+1 -> slot c+4
// ---------------------------------------------------------------------------
__global__ void k_prep(const float* __restrict__ W_t1, const float* __restrict__ W_t2,
                       const float* __restrict__ W_w1) {
    int tid = threadIdx.x;
    for (int i = tid; i < 8192; i += 256) {          // W1: n 0..127, k 0..63 (no sigma)
        int n = i >> 6, k = i & 63;
        float v = W_t1[k * 128 + n], hi, lo; tf32split(v, hi, lo);
        int pos = n * 64 + (k ^ ((n & 7) << 2));
        g_W1img[pos] = hi; g_W1img[8192 + pos] = lo;
    }
    for (int i = tid; i < 8192; i += 256) {          // W2: n 0..63, k 0..127 (sigma)
        int n = i >> 7, k = i & 127;
        float v = W_t2[k * 64 + n], hi, lo; tf32split(v, hi, lo);
        int j = k & 7;
        int slot = (j & 1) ? ((j >> 1) + 4) : (j >> 1);
        int kk = (k & ~7) | slot;
        int pos = n * 128 + (kk ^ ((n & 7) << 2));
        g_W2img[pos] = hi; g_W2img[8192 + pos] = lo;
    }
    for (int i = tid; i < 4096; i += 256) {          // W3: n 0..63, k 0..63 (sigma)
        int n = i >> 6, k = i & 63;
        float v = W_w1[k * 64 + n], hi, lo; tf32split(v, hi, lo);
        int j = k & 7;
        int slot = (j & 1) ? ((j >> 1) + 4) : (j >> 1);
        int kk = (k & ~7) | slot;
        int pos = n * 64 + (kk ^ ((n & 7) << 2));
        g_W3img[pos] = hi; g_W3img[4096 + pos] = lo;
    }
}

// ---------------------------------------------------------------------------
// Kernel 1: mean of particles_init * 0.1
// ---------------------------------------------------------------------------
__global__ void k_mean(const float* __restrict__ X) {
    int b = blockIdx.x;
    int tid = threadIdx.x;
    int q = tid >> 4, d4 = tid & 15;
    const float4* base = (const float4*)(X + (size_t)b * NP * 64);
    float4 acc = make_float4(0.f, 0.f, 0.f, 0.f);
    for (int n = q; n < NP; n += 16) {
        float4 v = base[n * 16 + d4];
        acc.x += v.x; acc.y += v.y; acc.z += v.z; acc.w += v.w;
    }
    __shared__ float s[16][64];
    *(float4*)&s[q][d4 * 4] = acc;
    __syncthreads();
    if (tid < 64) {
        float sum = 0.f;
        #pragma unroll
        for (int i = 0; i < 16; i++) sum += s[i][tid];
        g_mean[b * 64 + tid] = sum * (0.1f / 1000.0f);
    }
}

// ---------------------------------------------------------------------------
// Kernel 2: obs encoder, regime softmax, fused per-batch biases
// ---------------------------------------------------------------------------
__global__ void k_small(const float* __restrict__ obs,
                        const float* __restrict__ W_obs1, const float* __restrict__ b_obs1,
                        const float* __restrict__ W_obs2, const float* __restrict__ b_obs2,
                        const float* __restrict__ W_t1,   const float* __restrict__ b_t1,
                        const float* __restrict__ W_w1,   const float* __restrict__ b_w1,
                        const float* __restrict__ W_r,    const float* __restrict__ b_r,
                        float* __restrict__ out, int write_probs) {
    int b = blockIdx.x, tid = threadIdx.x;
    __shared__ float obs_s[256], h[128], enc[64], probs[4], m[64];
    obs_s[tid]       = obs[b * 256 + tid];
    obs_s[tid + 128] = obs[b * 256 + 128 + tid];
    if (tid < 64) m[tid] = g_mean[b * 64 + tid];
    __syncthreads();
    {
        float acc = b_obs1[tid];
        for (int j = 0; j < 256; j++) acc = fmaf(obs_s[j], W_obs1[j * 128 + tid], acc);
        h[tid] = gelu_exact(acc);
    }
    __syncthreads();
    if (tid < 64) {
        float a2 = b_obs2[tid];
        for (int j = 0; j < 128; j++) a2 = fmaf(h[j], W_obs2[j * 64 + tid], a2);
        enc[tid] = a2;
    }
    if (tid >= 64 && tid < 68) {
        int k = tid - 64;
        float lg = b_r[k];
        for (int d = 0; d < 64; d++) lg = fmaf(m[d], W_r[d * 4 + k], lg);
        probs[k] = lg;
    }
    __syncthreads();
    if (tid == 0) {
        float mx = fmaxf(fmaxf(probs[0], probs[1]), fmaxf(probs[2], probs[3]));
        float e0 = expf(probs[0] - mx), e1 = expf(probs[1] - mx);
        float e2 = expf(probs[2] - mx), e3 = expf(probs[3] - mx);
        float z = e0 + e1 + e2 + e3;
        probs[0] = e0 / z; probs[1] = e1 / z; probs[2] = e2 / z; probs[3] = e3 / z;
    }
    __syncthreads();
    {
        float bb = b_t1[tid];
        #pragma unroll
        for (int k = 0; k < 4; k++) bb = fmaf(probs[k], W_t1[(64 + k) * 128 + tid], bb);
        g_bias1[b * 128 + tid] = bb;
    }
    if (tid < 64) {
        float ob = b_w1[tid];
        for (int j = 0; j < 64; j++) ob = fmaf(enc[j], W_w1[(64 + j) * 64 + tid], ob);
        g_obsbias[b * 64 + tid] = ob;
    }
    if (write_probs && tid < 4) out[BQ * 64 + b * 4 + tid] = probs[tid];
}

// ---------------------------------------------------------------------------
// Kernel 3: fused MLP chain via mma.sync 3xTF32. One CTA per batch, 8 tiles.
// Warp (rw = warp>>1, cw = warp&1): rows 32*rw..+31, stage1 cols 64*cw..+63.
// Stage chaining stays in registers via sigma-permuted weight images.
// ---------------------------------------------------------------------------
__global__ void __launch_bounds__(256, 1)
k_big(const float* __restrict__ X, const float* __restrict__ b_t2,
      const float* __restrict__ W_w2, const float* __restrict__ b_w2) {
    extern __shared__ float sm[];
    int tid = threadIdx.x, b = blockIdx.x;
    int warp = tid >> 5, lane = tid & 31;
    int rw = warp >> 1, cw = warp & 1;
    int q = lane >> 2, cq = lane & 3, xm = q << 2;

    {   // weight images -> smem
        float4* d = (float4*)sm;
        const float4* s1 = (const float4*)g_W1img;
        for (int i = tid; i < 4096; i += 256) d[i] = s1[i];
        const float4* s2 = (const float4*)g_W2img;
        for (int i = tid; i < 4096; i += 256) d[4096 + i] = s2[i];
        const float4* s3 = (const float4*)g_W3img;
        for (int i = tid; i < 2048; i += 256) d[8192 + i] = s3[i];
    }
    if (tid < 128) sm[SBIAS1 + tid] = g_bias1[b * 128 + tid];
    else if (tid < 192) sm[SBT2 + tid - 128] = b_t2[tid - 128];
    else sm[SOBIAS + tid - 192] = g_obsbias[b * 64 + tid - 192];
    if (tid < 64) sm[SW4 + tid] = W_w2[tid];
    float bw = b_w2[0];
    __syncthreads();

    const float* W1h = sm + SW1H; const float* W1l = sm + SW1L;
    const float* W2h = sm + SW2H; const float* W2l = sm + SW2L;
    const float* W3h = sm + SW3H; const float* W3l = sm + SW3L;
    float* exch = sm + SEXCH + rw * 2176;

    const float* Xb = X + (size_t)b * NP * 64;

    for (int t = 0; t < 8; t++) {
        int n0 = t * 128;

        // ================= stage 1: D1 = 0.1X @ W1 (cols 64cw..64cw+63) ======
        float acc1[2][8][4];
        #pragma unroll
        for (int rt = 0; rt < 2; rt++)
            #pragma unroll
            for (int c = 0; c < 8; c++)
                #pragma unroll
                for (int r = 0; r < 4; r++) acc1[rt][c][r] = 0.f;

        for (int kt = 0; kt < 8; kt++) {
            u32 ah[2][4], al[2][4];
            #pragma unroll
            for (int rt = 0; rt < 2; rt++) {
                int r0 = 32 * rw + 16 * rt + q, r1 = r0 + 8;
                int kb = kt * 8 + cq;
                float x0 = 0.f, x1 = 0.f, x2 = 0.f, x3 = 0.f;
                if (n0 + r0 < NP) { x0 = Xb[(size_t)(n0 + r0) * 64 + kb];
                                    x2 = Xb[(size_t)(n0 + r0) * 64 + kb + 4]; }
                if (n0 + r1 < NP) { x1 = Xb[(size_t)(n0 + r1) * 64 + kb];
                                    x3 = Xb[(size_t)(n0 + r1) * 64 + kb + 4]; }
                float h0, l0, h1, l1, h2, l2, h3, l3;
                tf32split(0.1f * x0, h0, l0); tf32split(0.1f * x1, h1, l1);
                tf32split(0.1f * x2, h2, l2); tf32split(0.1f * x3, h3, l3);
                ah[rt][0] = __float_as_uint(h0); ah[rt][1] = __float_as_uint(h1);
                ah[rt][2] = __float_as_uint(h2); ah[rt][3] = __float_as_uint(h3);
                al[rt][0] = __float_as_uint(l0); al[rt][1] = __float_as_uint(l1);
                al[rt][2] = __float_as_uint(l2); al[rt][3] = __float_as_uint(l3);
            }
            #pragma unroll
            for (int ct = 0; ct < 8; ct++) {
                int nb = (64 * cw + 8 * ct + q) * 64;
                int o0 = (8 * kt + cq) ^ xm, o1 = (8 * kt + cq + 4) ^ xm;
                u32 bh0 = __float_as_uint(W1h[nb + o0]);
                u32 bh1 = __float_as_uint(W1h[nb + o1]);
                u32 bl0 = __float_as_uint(W1l[nb + o0]);
                u32 bl1 = __float_as_uint(W1l[nb + o1]);
                #pragma unroll
                for (int rt = 0; rt < 2; rt++) {
                    mma8(acc1[rt][ct], ah[rt][0], ah[rt][1], ah[rt][2], ah[rt][3], bh0, bh1);
                    mma8(acc1[rt][ct], al[rt][0], al[rt][1], al[rt][2], al[rt][3], bh0, bh1);
                    mma8(acc1[rt][ct], ah[rt][0], ah[rt][1], ah[rt][2], ah[rt][3], bl0, bl1);
                }
            }
        }

        // ================= stage 2: partial D2 over k = own 64 cols ==========
        // A-frags from acc1 d-regs: (a0,a1,a2,a3) = (g(d0), g(d2), g(d1), g(d3))
        float acc2[2][8][4];
        #pragma unroll
        for (int rt = 0; rt < 2; rt++)
            #pragma unroll
            for (int c = 0; c < 8; c++)
                #pragma unroll
                for (int r = 0; r < 4; r++) acc2[rt][c][r] = 0.f;

        #pragma unroll
        for (int kt2 = 0; kt2 < 8; kt2++) {
            int c0 = 64 * cw + 8 * kt2 + 2 * cq;
            float bb0 = sm[SBIAS1 + c0], bb1 = sm[SBIAS1 + c0 + 1];
            u32 ah[2][4], al[2][4];
            #pragma unroll
            for (int rt = 0; rt < 2; rt++) {
                float g0 = gelu_exact(acc1[rt][kt2][0] + bb0);
                float g1 = gelu_exact(acc1[rt][kt2][1] + bb1);
                float g2 = gelu_exact(acc1[rt][kt2][2] + bb0);
                float g3 = gelu_exact(acc1[rt][kt2][3] + bb1);
                float h0, l0, h1, l1, h2, l2, h3, l3;
                tf32split(g0, h0, l0); tf32split(g2, h1, l1);   // a1 <- d2
                tf32split(g1, h2, l2);                          // a2 <- d1
                tf32split(g3, h3, l3);
                ah[rt][0] = __float_as_uint(h0); ah[rt][1] = __float_as_uint(h1);
                ah[rt][2] = __float_as_uint(h2); ah[rt][3] = __float_as_uint(h3);
                al[rt][0] = __float_as_uint(l0); al[rt][1] = __float_as_uint(l1);
                al[rt][2] = __float_as_uint(l2); al[rt][3] = __float_as_uint(l3);
            }
            int kg0 = (64 * cw + 8 * kt2 + cq) ^ xm;
            int kg1 = (64 * cw + 8 * kt2 + cq + 4) ^ xm;
            #pragma unroll
            for (int nt = 0; nt < 8; nt++) {
                int nb = (8 * nt + q) * 128;
                u32 bh0 = __float_as_uint(W2h[nb + kg0]);
                u32 bh1 = __float_as_uint(W2h[nb + kg1]);
                u32 bl0 = __float_as_uint(W2l[nb + kg0]);
                u32 bl1 = __float_as_uint(W2l[nb + kg1]);
                #pragma unroll
                for (int rt = 0; rt < 2; rt++) {
                    mma8(acc2[rt][nt], ah[rt][0], ah[rt][1], ah[rt][2], ah[rt][3], bh0, bh1);
                    mma8(acc2[rt][nt], al[rt][0], al[rt][1], al[rt][2], al[rt][3], bh0, bh1);
                    mma8(acc2[rt][nt], ah[rt][0], ah[rt][1], ah[rt][2], ah[rt][3], bl0, bl1);
                }
            }
        }

        // ---- exchange: P2 = partial(cw0) + partial(cw1) + b_t2, both warps ----
        if (cw == 0) {
            #pragma unroll
            for (int rt = 0; rt < 2; rt++)
                #pragma unroll
                for (int nt = 0; nt < 8; nt++)
                    *(float4*)&exch[lane * 68 + rt * 32 + nt * 4] =
                        make_float4(acc2[rt][nt][0], acc2[rt][nt][1],
                                    acc2[rt][nt][2], acc2[rt][nt][3]);
        }
        __syncthreads();
        if (cw == 1) {
            #pragma unroll
            for (int rt = 0; rt < 2; rt++)
                #pragma unroll
                for (int nt = 0; nt < 8; nt++) {
                    float4 v = *(float4*)&exch[lane * 68 + rt * 32 + nt * 4];
                    float t0 = sm[SBT2 + 8 * nt + 2 * cq], t1 = sm[SBT2 + 8 * nt + 2 * cq + 1];
                    acc2[rt][nt][0] += v.x + t0;
                    acc2[rt][nt][1] += v.y + t1;
                    acc2[rt][nt][2] += v.z + t0;
                    acc2[rt][nt][3] += v.w + t1;
                    *(float4*)&exch[lane * 68 + rt * 32 + nt * 4] =
                        make_float4(acc2[rt][nt][0], acc2[rt][nt][1],
                                    acc2[rt][nt][2], acc2[rt][nt][3]);
                }
        }
        __syncthreads();
        if (cw == 0) {
            #pragma unroll
            for (int rt = 0; rt < 2; rt++)
                #pragma unroll
                for (int nt = 0; nt < 8; nt++) {
                    float4 v = *(float4*)&exch[lane * 68 + rt * 32 + nt * 4];
                    acc2[rt][nt][0] = v.x; acc2[rt][nt][1] = v.y;
                    acc2[rt][nt][2] = v.z; acc2[rt][nt][3] = v.w;
                }
        }

        // ================= stage 3: partial D3 over k-half = 4cw..4cw+3 ======
        float acc3[2][8][4];
        #pragma unroll
        for (int rt = 0; rt < 2; rt++)
            #pragma unroll
            for (int c = 0; c < 8; c++)
                #pragma unroll
                for (int r = 0; r < 4; r++) acc3[rt][c][r] = 0.f;

        #pragma unroll
        for (int j = 0; j < 4; j++) {
            u32 ah[2][4], al[2][4];
            #pragma unroll
            for (int rt = 0; rt < 2; rt++) {
                float d0 = cw ? acc2[rt][4 + j][0] : acc2[rt][j][0];
                float d1 = cw ? acc2[rt][4 + j][1] : acc2[rt][j][1];
                float d2 = cw ? acc2[rt][4 + j][2] : acc2[rt][j][2];
                float d3 = cw ? acc2[rt][4 + j][3] : acc2[rt][j][3];
                float h0, l0, h1, l1, h2, l2, h3, l3;
                tf32split(d0, h0, l0); tf32split(d2, h1, l1);
                tf32split(d1, h2, l2); tf32split(d3, h3, l3);
                ah[rt][0] = __float_as_uint(h0); ah[rt][1] = __float_as_uint(h1);
                ah[rt][2] = __float_as_uint(h2); ah[rt][3] = __float_as_uint(h3);
                al[rt][0] = __float_as_uint(l0); al[rt][1] = __float_as_uint(l1);
                al[rt][2] = __float_as_uint(l2); al[rt][3] = __float_as_uint(l3);
            }
            int ktg = 4 * cw + j;
            int kg0 = (8 * ktg + cq) ^ xm, kg1 = (8 * ktg + cq + 4) ^ xm;
            #pragma unroll
            for (int nt = 0; nt < 8; nt++) {
                int nb = (8 * nt + q) * 64;
                u32 bh0 = __float_as_uint(W3h[nb + kg0]);
                u32 bh1 = __float_as_uint(W3h[nb + kg1]);
                u32 bl0 = __float_as_uint(W3l[nb + kg0]);
                u32 bl1 = __float_as_uint(W3l[nb + kg1]);
                #pragma unroll
                for (int rt = 0; rt < 2; rt++) {
                    mma8(acc3[rt][nt], ah[rt][0], ah[rt][1], ah[rt][2], ah[rt][3], bh0, bh1);
                    mma8(acc3[rt][nt], al[rt][0], al[rt][1], al[rt][2], al[rt][3], bh0, bh1);
                    mma8(acc3[rt][nt], ah[rt][0], ah[rt][1], ah[rt][2], ah[rt][3], bl0, bl1);
                }
            }
        }

        // ---- stage 4: combine halves, gelu, dot w4, row-reduce, store ----
        if (cw == 0) {
            #pragma unroll
            for (int rt = 0; rt < 2; rt++)
                #pragma unroll
                for (int nt = 0; nt < 8; nt++)
                    *(float4*)&exch[lane * 68 + rt * 32 + nt * 4] =
                        make_float4(acc3[rt][nt][0], acc3[rt][nt][1],
                                    acc3[rt][nt][2], acc3[rt][nt][3]);
        }
        __syncthreads();
        if (cw == 1) {
            #pragma unroll
            for (int rt = 0; rt < 2; rt++) {
                float pa = 0.f, pb = 0.f;
                #pragma unroll
                for (int nt = 0; nt < 8; nt++) {
                    float4 v = *(float4*)&exch[lane * 68 + rt * 32 + nt * 4];
                    int nc = 8 * nt + 2 * cq;
                    float ob0 = sm[SOBIAS + nc], ob1 = sm[SOBIAS + nc + 1];
                    float w40 = sm[SW4 + nc],   w41 = sm[SW4 + nc + 1];
                    pa = fmaf(gelu_exact(acc3[rt][nt][0] + v.x + ob0), w40, pa);
                    pa = fmaf(gelu_exact(acc3[rt][nt][1] + v.y + ob1), w41, pa);
                    pb = fmaf(gelu_exact(acc3[rt][nt][2] + v.z + ob0), w40, pb);
                    pb = fmaf(gelu_exact(acc3[rt][nt][3] + v.w + ob1), w41, pb);
                }
                pa += __shfl_xor_sync(0xffffffffu, pa, 1);
                pa += __shfl_xor_sync(0xffffffffu, pa, 2);
                pb += __shfl_xor_sync(0xffffffffu, pb, 1);
                pb += __shfl_xor_sync(0xffffffffu, pb, 2);
                if (cq == 0) {
                    int r0 = n0 + 32 * rw + 16 * rt + q;
                    if (r0 < NP)     g_logw[b * NP + r0]     = pa + bw;
                    if (r0 + 8 < NP) g_logw[b * NP + r0 + 8] = pb + bw;
                }
            }
        }
        __syncthreads();
    }
}

// ---------------------------------------------------------------------------
// Kernel 4: softmax + top-32 + commuted weighted recompute (unchanged)
// ---------------------------------------------------------------------------
__global__ void __launch_bounds__(256, 1)
k_final(const float* __restrict__ X,
        const float* __restrict__ W_t1, const float* __restrict__ W_t2,
        const float* __restrict__ b_t2, float* __restrict__ out) {
    extern __shared__ float smf[];
    float* W1s   = smf;
    float* W2s   = W1s + 8192;
    float* lw    = W2s + 8192;
    float* bias1 = lw + 1024;
    float* bt2s  = bias1 + 128;
    float* xr    = bt2s + 64;
    float* h1s   = xr + 2048;
    float* hbar  = h1s + 4224;
    float* red2  = hbar + 128;
    float* red   = red2 + 256;
    int*   redi  = (int*)(red + 8);
    float* selw  = (float*)(redi + 8);
    int*   seli  = (int*)(selw + 32);
    float* bcast = (float*)(seli + 32);

    int b = blockIdx.x, tid = threadIdx.x;
    int lane = tid & 31, warp = tid >> 5;

    for (int i = tid; i < 8192; i += 256) { W1s[i] = W_t1[i]; W2s[i] = W_t2[i]; }
    if (tid < 128) bias1[tid] = g_bias1[b * 128 + tid];
    if (tid < 64)  bt2s[tid]  = b_t2[tid];
    for (int i = tid; i < 1024; i += 256)
        lw[i] = (i < NP) ? g_logw[b * NP + i] : -INFINITY;
    __syncthreads();

    float lmax = -INFINITY;
    #pragma unroll
    for (int m = 0; m < 4; m++) lmax = fmaxf(lmax, lw[tid + 256 * m]);
    #pragma unroll
    for (int off = 16; off >= 1; off >>= 1)
        lmax = fmaxf(lmax, __shfl_xor_sync(0xffffffffu, lmax, off));
    if (lane == 0) red[warp] = lmax;
    __syncthreads();
    if (tid == 0) {
        float mx = red[0];
        for (int w = 1; w < 8; w++) mx = fmaxf(mx, red[w]);
        bcast[0] = mx;
    }
    __syncthreads();
    float mx = bcast[0];

    float ls = 0.f;
    #pragma unroll
    for (int m = 0; m < 4; m++) ls += expf(lw[tid + 256 * m] - mx);
    #pragma unroll
    for (int off = 16; off >= 1; off >>= 1)
        ls += __shfl_xor_sync(0xffffffffu, ls, off);
    if (lane == 0) red[warp] = ls;
    __syncthreads();
    if (tid == 0) {
        float z = 0.f;
        for (int w = 0; w < 8; w++) z += red[w];
        bcast[1] = z;
        bcast[2] = 0.f;
    }
    __syncthreads();
    float Z = bcast[1];

    for (int it = 0; it < TOPK; it++) {
        float v = -INFINITY; int vi = 0x7fffffff;
        #pragma unroll
        for (int m = 0; m < 4; m++) {
            int i = tid + 256 * m;
            float x = lw[i];
            if (x > v || (x == v && i < vi)) { v = x; vi = i; }
        }
        #pragma unroll
        for (int off = 16; off >= 1; off >>= 1) {
            float ov = __shfl_xor_sync(0xffffffffu, v, off);
            int   oi = __shfl_xor_sync(0xffffffffu, vi, off);
            if (ov > v || (ov == v && oi < vi)) { v = ov; vi = oi; }
        }
        if (lane == 0) { red[warp] = v; redi[warp] = vi; }
        __syncthreads();
        if (tid == 0) {
            float bv = red[0]; int bi = redi[0];
            for (int w = 1; w < 8; w++)
                if (red[w] > bv || (red[w] == bv && redi[w] < bi)) { bv = red[w]; bi = redi[w]; }
            seli[it] = bi;
            float wv = expf(bv - mx) / Z;
            selw[it] = wv;
            bcast[2] += wv;
            lw[bi] = -INFINITY;
        }
        __syncthreads();
    }

    for (int i = tid; i < TOPK * 16; i += 256) {
        int s = i >> 4, d4 = i & 15;
        float4 v = ((const float4*)(X + ((size_t)b * NP + seli[s]) * 64))[d4];
        *(float4*)&xr[s * 64 + d4 * 4] =
            make_float4(0.1f * v.x, 0.1f * v.y, 0.1f * v.z, 0.1f * v.w);
    }
    __syncthreads();

    {
        int s0 = (tid >> 4) * 2;
        int c0 = (tid & 15) * 8;
        u64 accA[8];
        #pragma unroll
        for (int j = 0; j < 8; j++) accA[j] = 0ull;
        #pragma unroll 4
        for (int k = 0; k < 64; k++) {
            u64 xp = pack2(xr[s0 * 64 + k], xr[s0 * 64 + 64 + k]);
            float4 b0 = *(const float4*)&W1s[k * 128 + c0];
            float4 b1 = *(const float4*)&W1s[k * 128 + c0 + 4];
            u64 bs[8] = {splat2(b0.x), splat2(b0.y), splat2(b0.z), splat2(b0.w),
                         splat2(b1.x), splat2(b1.y), splat2(b1.z), splat2(b1.w)};
            #pragma unroll
            for (int j = 0; j < 8; j++) fma2(accA[j], xp, bs[j]);
        }
        #pragma unroll
        for (int j = 0; j < 8; j++) {
            int col = c0 + j;
            float lo, hi; unpack2(accA[j], lo, hi);
            float bb = bias1[col];
            h1s[s0 * 132 + col]       = gelu_exact(lo + bb);
            h1s[(s0 + 1) * 132 + col] = gelu_exact(hi + bb);
        }
    }
    __syncthreads();

    if (tid < 128) {
        float a = 0.f;
        #pragma unroll 8
        for (int s = 0; s < TOPK; s++) a = fmaf(selw[s], h1s[s * 132 + tid], a);
        hbar[tid] = a;
    }
    __syncthreads();

    {
        int d = tid & 63, jg = tid >> 6;
        float a = 0.f;
        #pragma unroll 8
        for (int jj = 0; jj < 32; jj++) {
            int j = jg * 32 + jj;
            a = fmaf(hbar[j], W2s[j * 64 + d], a);
        }
        red2[jg * 64 + d] = a;
    }
    __syncthreads();
    if (tid < 64) {
        float sumw = bcast[2];
        out[b * 64 + tid] = red2[tid] + red2[64 + tid] + red2[128 + tid]
                          + red2[192 + tid] + sumw * bt2s[tid];
    }
}

// ---------------------------------------------------------------------------
extern "C" void kernel_launch(void* const* d_in, const int* in_sizes, int n_in,
                              void* d_out, int out_size) {
    const float* obs    = (const float*)d_in[0];
    const float* X      = (const float*)d_in[1];
    const float* W_obs1 = (const float*)d_in[2];
    const float* b_obs1 = (const float*)d_in[3];
    const float* W_obs2 = (const float*)d_in[4];
    const float* b_obs2 = (const float*)d_in[5];
    const float* W_t1   = (const float*)d_in[6];
    const float* b_t1   = (const float*)d_in[7];
    const float* W_t2   = (const float*)d_in[8];
    const float* b_t2   = (const float*)d_in[9];
    const float* W_w1   = (const float*)d_in[10];
    const float* b_w1   = (const float*)d_in[11];
    const float* W_w2   = (const float*)d_in[12];
    const float* b_w2   = (const float*)d_in[13];
    const float* W_r    = (const float*)d_in[14];
    const float* b_r    = (const float*)d_in[15];
    float* out = (float*)d_out;

    size_t sm_fin = (size_t)(8192 + 8192 + 1024 + 128 + 64 + 2048 + 4224
                             + 128 + 256 + 8 + 8 + 32 + 32 + 4 + 32) * sizeof(float);
    cudaFuncSetAttribute(k_big,   cudaFuncAttributeMaxDynamicSharedMemorySize, SMEM_BIG_BYTES);
    cudaFuncSetAttribute(k_final, cudaFuncAttributeMaxDynamicSharedMemorySize, (int)sm_fin);

    int write_probs = (out_size >= BQ * 64 + BQ * 4) ? 1 : 0;

    k_prep<<<1, 256>>>(W_t1, W_t2, W_w1);
    k_mean<<<BQ, 256>>>(X);
    k_small<<<BQ, 128>>>(obs, W_obs1, b_obs1, W_obs2, b_obs2,
                         W_t1, b_t1, W_w1, b_w1, W_r, b_r, out, write_probs);
    k_big<<<BQ, 256, SMEM_BIG_BYTES>>>(X, b_t2, W_w2, b_w2);
    k_final<<<BQ, 256, sm_fin>>>(X, W_t1, W_t2, b_t2, out);
}